// round 1
// baseline (speedup 1.0000x reference)
#include <cuda_runtime.h>
#include <math.h>

#define BB 4
#define TT 4096
#define CC 1024
#define HH 128
#define BM 64
#define BN 64
#define NQT (TT / BM)   // 64

// scratch: q,k,v projections (25.2 MB total) — __device__ globals (no alloc)
__device__ float g_q[BB * TT * HH];
__device__ float g_k[BB * TT * HH];
__device__ float g_v[BB * TT * HH];

// ---------------------------------------------------------------------------
// Projection: y = x @ W  (M = B*T = 16384, K = C = 1024, N = H = 128)
// grid (M/64, 3), block 256. BK=32. Thread tile 4 rows x 8 cols (cols tx+16j).
// ---------------------------------------------------------------------------
__global__ void __launch_bounds__(256) proj_kernel(
    const float* __restrict__ x,
    const float* __restrict__ Wk,
    const float* __restrict__ Wq,
    const float* __restrict__ Wv)
{
    __shared__ float Xs[64][32];
    __shared__ float Ws[32][128];

    const float* W;
    float* y;
    int z = blockIdx.y;
    if (z == 0)      { W = Wq; y = g_q; }
    else if (z == 1) { W = Wk; y = g_k; }
    else             { W = Wv; y = g_v; }

    const int row0 = blockIdx.x * 64;
    const int tid = threadIdx.x;
    const int ty = tid >> 4, tx = tid & 15;

    float acc[4][8];
#pragma unroll
    for (int i = 0; i < 4; i++)
#pragma unroll
        for (int j = 0; j < 8; j++) acc[i][j] = 0.f;

    for (int k0 = 0; k0 < CC; k0 += 32) {
        // load X tile 64x32: 512 float4, 2 per thread
#pragma unroll
        for (int u = 0; u < 2; u++) {
            int v = tid + u * 256;
            int r = v >> 3, c4 = (v & 7) << 2;
            *(float4*)&Xs[r][c4] =
                *(const float4*)&x[(size_t)(row0 + r) * CC + k0 + c4];
        }
        // load W tile 32x128: 1024 float4, 4 per thread
#pragma unroll
        for (int u = 0; u < 4; u++) {
            int v = tid + u * 256;
            int r = v >> 5, c4 = (v & 31) << 2;
            *(float4*)&Ws[r][c4] =
                *(const float4*)&W[(size_t)(k0 + r) * HH + c4];
        }
        __syncthreads();
#pragma unroll
        for (int kk = 0; kk < 32; kk++) {
            float a[4], b[8];
#pragma unroll
            for (int i = 0; i < 4; i++) a[i] = Xs[ty * 4 + i][kk];
#pragma unroll
            for (int j = 0; j < 8; j++) b[j] = Ws[kk][tx + 16 * j];
#pragma unroll
            for (int i = 0; i < 4; i++)
#pragma unroll
                for (int j = 0; j < 8; j++) acc[i][j] += a[i] * b[j];
        }
        __syncthreads();
    }
#pragma unroll
    for (int i = 0; i < 4; i++) {
        float* yp = &y[(size_t)(row0 + ty * 4 + i) * HH];
#pragma unroll
        for (int j = 0; j < 8; j++) yp[tx + 16 * j] = acc[i][j];
    }
}

// ---------------------------------------------------------------------------
// Flash attention (causal), fp32. One CTA per (b, q-tile of 64 rows).
// 256 threads: thread (ty,tx) owns S rows ty*4+i, S cols tx+16j,
// O rows ty*4+i, O cols tx+16jj. Softmax in base-2 domain.
// ---------------------------------------------------------------------------
__global__ void __launch_bounds__(256) attn_kernel(float* __restrict__ out)
{
    extern __shared__ float sm[];
    const int SQ = 132;   // padded row stride for Q/K/V tiles
    const int SP = 68;    // padded row stride for P tile
    float* Qs = sm;                  // [64][132]
    float* Ks = Qs + 64 * SQ;        // [64][132]
    float* Vs = Ks + 64 * SQ;        // [64][132]
    float* Ps = Vs + 64 * SQ;        // [64][68]

    const int bid = blockIdx.x;
    const int b = bid & 3;                 // B = 4
    const int qt = NQT - 1 - (bid >> 2);   // biggest tiles scheduled first
    const int q0 = qt * BM;
    const int tid = threadIdx.x;
    const int ty = tid >> 4, tx = tid & 15;

    // load Q tile, folding (H^-0.5 * log2(e)) so softmax uses exp2
    const float qscale = 1.4426950408889634f * 0.08838834764831845f;
    {
        const float* qptr = &g_q[((size_t)b * TT + q0) * HH];
#pragma unroll
        for (int u = 0; u < 8; u++) {
            int v = tid + u * 256;          // 2048 float4 total
            int r = v >> 5, c4 = (v & 31) << 2;
            float4 t = *(const float4*)&qptr[(size_t)r * HH + c4];
            t.x *= qscale; t.y *= qscale; t.z *= qscale; t.w *= qscale;
            *(float4*)&Qs[r * SQ + c4] = t;
        }
    }

    float m_i[4], l_i[4], o[4][8];
#pragma unroll
    for (int i = 0; i < 4; i++) {
        m_i[i] = -1e30f; l_i[i] = 0.f;
#pragma unroll
        for (int j = 0; j < 8; j++) o[i][j] = 0.f;
    }
    __syncthreads();

    for (int kt = 0; kt <= qt; kt++) {
        const int k0 = kt * BN;
        const float* kptr = &g_k[((size_t)b * TT + k0) * HH];
        const float* vptr = &g_v[((size_t)b * TT + k0) * HH];
#pragma unroll
        for (int u = 0; u < 8; u++) {
            int v = tid + u * 256;
            int r = v >> 5, c4 = (v & 31) << 2;
            *(float4*)&Ks[r * SQ + c4] = *(const float4*)&kptr[(size_t)r * HH + c4];
            *(float4*)&Vs[r * SQ + c4] = *(const float4*)&vptr[(size_t)r * HH + c4];
        }
        __syncthreads();

        // ---- S = Q @ K^T (dot4 over h) ----
        float s[4][4];
#pragma unroll
        for (int i = 0; i < 4; i++)
#pragma unroll
            for (int j = 0; j < 4; j++) s[i][j] = 0.f;

#pragma unroll
        for (int h = 0; h < HH; h += 4) {
            float4 a[4], kb[4];
#pragma unroll
            for (int i = 0; i < 4; i++)
                a[i] = *(const float4*)&Qs[(ty * 4 + i) * SQ + h];
#pragma unroll
            for (int j = 0; j < 4; j++)
                kb[j] = *(const float4*)&Ks[(tx + 16 * j) * SQ + h];
#pragma unroll
            for (int i = 0; i < 4; i++)
#pragma unroll
                for (int j = 0; j < 4; j++) {
                    s[i][j] += a[i].x * kb[j].x;
                    s[i][j] += a[i].y * kb[j].y;
                    s[i][j] += a[i].z * kb[j].z;
                    s[i][j] += a[i].w * kb[j].w;
                }
        }

        // causal mask only on the diagonal tile (k0 == q0)
        if (kt == qt) {
#pragma unroll
            for (int i = 0; i < 4; i++) {
                int r = ty * 4 + i;
#pragma unroll
                for (int j = 0; j < 4; j++)
                    if (tx + 16 * j > r) s[i][j] = -1e30f;
            }
        }

        // ---- online softmax (base-2) + write P ----
#pragma unroll
        for (int i = 0; i < 4; i++) {
            float mx = fmaxf(fmaxf(s[i][0], s[i][1]), fmaxf(s[i][2], s[i][3]));
#pragma unroll
            for (int off = 8; off >= 1; off >>= 1)
                mx = fmaxf(mx, __shfl_xor_sync(0xffffffffu, mx, off));
            float m_new = fmaxf(m_i[i], mx);
            float alpha = exp2f(m_i[i] - m_new);
            float rs = 0.f;
#pragma unroll
            for (int j = 0; j < 4; j++) {
                s[i][j] = exp2f(s[i][j] - m_new);
                rs += s[i][j];
            }
#pragma unroll
            for (int off = 8; off >= 1; off >>= 1)
                rs += __shfl_xor_sync(0xffffffffu, rs, off);
            l_i[i] = l_i[i] * alpha + rs;
            m_i[i] = m_new;
#pragma unroll
            for (int jj = 0; jj < 8; jj++) o[i][jj] *= alpha;
#pragma unroll
            for (int j = 0; j < 4; j++)
                Ps[(ty * 4 + i) * SP + tx + 16 * j] = s[i][j];
        }
        __syncthreads();

        // ---- O += P @ V ----
#pragma unroll 4
        for (int n = 0; n < BN; n++) {
            float p[4], vv[8];
#pragma unroll
            for (int i = 0; i < 4; i++) p[i] = Ps[(ty * 4 + i) * SP + n];
#pragma unroll
            for (int jj = 0; jj < 8; jj++) vv[jj] = Vs[n * SQ + tx + 16 * jj];
#pragma unroll
            for (int i = 0; i < 4; i++)
#pragma unroll
                for (int jj = 0; jj < 8; jj++) o[i][jj] += p[i] * vv[jj];
        }
        __syncthreads();   // protect K/V/P before next iteration's overwrite
    }

    // ---- epilogue: normalize and store ----
#pragma unroll
    for (int i = 0; i < 4; i++) {
        float inv = 1.f / l_i[i];
        float* op = &out[((size_t)b * TT + q0 + ty * 4 + i) * HH];
#pragma unroll
        for (int jj = 0; jj < 8; jj++)
            op[tx + 16 * jj] = o[i][jj] * inv;
    }
}

// ---------------------------------------------------------------------------
extern "C" void kernel_launch(void* const* d_in, const int* in_sizes, int n_in,
                              void* d_out, int out_size)
{
    const float* x  = (const float*)d_in[0];
    const float* Wk = (const float*)d_in[1];
    const float* Wq = (const float*)d_in[2];
    const float* Wv = (const float*)d_in[3];
    float* out = (float*)d_out;

    (void)in_sizes; (void)n_in; (void)out_size;

    // projections: q,k,v
    dim3 pgrid((BB * TT) / 64, 3);
    proj_kernel<<<pgrid, 256>>>(x, Wk, Wq, Wv);

    // attention
    const int smem_bytes = (64 * 132 * 3 + 64 * 68) * 4;   // 118784
    cudaFuncSetAttribute(attn_kernel,
                         cudaFuncAttributeMaxDynamicSharedMemorySize,
                         smem_bytes);
    attn_kernel<<<BB * NQT, 256, smem_bytes>>>(out);
}

// round 2
// speedup vs baseline: 1.0026x; 1.0026x over previous
#include <cuda_runtime.h>
#include <math.h>

#define BB 4
#define TT 4096
#define CC 1024
#define HH 128
#define BM 64
#define BN 64
#define NQT (TT / BM)   // 64

// scratch: q,k,v projections (25.2 MB total) — __device__ globals (no alloc)
__device__ float g_q[BB * TT * HH];
__device__ float g_k[BB * TT * HH];
__device__ float g_v[BB * TT * HH];

// ---------------------------------------------------------------------------
// Projection: y = x @ W  (M = B*T = 16384, K = C = 1024, N = H = 128)
// grid (M/64, 3), block 256. BK=32. Thread tile 4 rows x 8 cols (cols tx+16j).
// ---------------------------------------------------------------------------
__global__ void __launch_bounds__(256) proj_kernel(
    const float* __restrict__ x,
    const float* __restrict__ Wk,
    const float* __restrict__ Wq,
    const float* __restrict__ Wv)
{
    __shared__ float Xs[64][32];
    __shared__ float Ws[32][128];

    const float* W;
    float* y;
    int z = blockIdx.y;
    if (z == 0)      { W = Wq; y = g_q; }
    else if (z == 1) { W = Wk; y = g_k; }
    else             { W = Wv; y = g_v; }

    const int row0 = blockIdx.x * 64;
    const int tid = threadIdx.x;
    const int ty = tid >> 4, tx = tid & 15;

    float acc[4][8];
#pragma unroll
    for (int i = 0; i < 4; i++)
#pragma unroll
        for (int j = 0; j < 8; j++) acc[i][j] = 0.f;

    for (int k0 = 0; k0 < CC; k0 += 32) {
        // load X tile 64x32: 512 float4, 2 per thread
#pragma unroll
        for (int u = 0; u < 2; u++) {
            int v = tid + u * 256;
            int r = v >> 3, c4 = (v & 7) << 2;
            *(float4*)&Xs[r][c4] =
                *(const float4*)&x[(size_t)(row0 + r) * CC + k0 + c4];
        }
        // load W tile 32x128: 1024 float4, 4 per thread
#pragma unroll
        for (int u = 0; u < 4; u++) {
            int v = tid + u * 256;
            int r = v >> 5, c4 = (v & 31) << 2;
            *(float4*)&Ws[r][c4] =
                *(const float4*)&W[(size_t)(k0 + r) * HH + c4];
        }
        __syncthreads();
#pragma unroll
        for (int kk = 0; kk < 32; kk++) {
            float a[4], b[8];
#pragma unroll
            for (int i = 0; i < 4; i++) a[i] = Xs[ty * 4 + i][kk];
#pragma unroll
            for (int j = 0; j < 8; j++) b[j] = Ws[kk][tx + 16 * j];
#pragma unroll
            for (int i = 0; i < 4; i++)
#pragma unroll
                for (int j = 0; j < 8; j++) acc[i][j] += a[i] * b[j];
        }
        __syncthreads();
    }
#pragma unroll
    for (int i = 0; i < 4; i++) {
        float* yp = &y[(size_t)(row0 + ty * 4 + i) * HH];
#pragma unroll
        for (int j = 0; j < 8; j++) yp[tx + 16 * j] = acc[i][j];
    }
}

// ---------------------------------------------------------------------------
// Flash attention (causal), fp32. One CTA per (b, q-tile of 64 rows).
// 256 threads: thread (ty,tx) owns S rows ty*4+i, S cols tx+16j,
// O rows ty*4+i, O cols tx+16jj. Softmax in base-2 domain.
// ---------------------------------------------------------------------------
__global__ void __launch_bounds__(256) attn_kernel(float* __restrict__ out)
{
    extern __shared__ float sm[];
    const int SQ = 132;   // padded row stride for Q/K/V tiles
    const int SP = 68;    // padded row stride for P tile
    float* Qs = sm;                  // [64][132]
    float* Ks = Qs + 64 * SQ;        // [64][132]
    float* Vs = Ks + 64 * SQ;        // [64][132]
    float* Ps = Vs + 64 * SQ;        // [64][68]

    const int bid = blockIdx.x;
    const int b = bid & 3;                 // B = 4
    const int qt = NQT - 1 - (bid >> 2);   // biggest tiles scheduled first
    const int q0 = qt * BM;
    const int tid = threadIdx.x;
    const int ty = tid >> 4, tx = tid & 15;

    // load Q tile, folding (H^-0.5 * log2(e)) so softmax uses exp2
    const float qscale = 1.4426950408889634f * 0.08838834764831845f;
    {
        const float* qptr = &g_q[((size_t)b * TT + q0) * HH];
#pragma unroll
        for (int u = 0; u < 8; u++) {
            int v = tid + u * 256;          // 2048 float4 total
            int r = v >> 5, c4 = (v & 31) << 2;
            float4 t = *(const float4*)&qptr[(size_t)r * HH + c4];
            t.x *= qscale; t.y *= qscale; t.z *= qscale; t.w *= qscale;
            *(float4*)&Qs[r * SQ + c4] = t;
        }
    }

    float m_i[4], l_i[4], o[4][8];
#pragma unroll
    for (int i = 0; i < 4; i++) {
        m_i[i] = -1e30f; l_i[i] = 0.f;
#pragma unroll
        for (int j = 0; j < 8; j++) o[i][j] = 0.f;
    }
    __syncthreads();

    for (int kt = 0; kt <= qt; kt++) {
        const int k0 = kt * BN;
        const float* kptr = &g_k[((size_t)b * TT + k0) * HH];
        const float* vptr = &g_v[((size_t)b * TT + k0) * HH];
#pragma unroll
        for (int u = 0; u < 8; u++) {
            int v = tid + u * 256;
            int r = v >> 5, c4 = (v & 31) << 2;
            *(float4*)&Ks[r * SQ + c4] = *(const float4*)&kptr[(size_t)r * HH + c4];
            *(float4*)&Vs[r * SQ + c4] = *(const float4*)&vptr[(size_t)r * HH + c4];
        }
        __syncthreads();

        // ---- S = Q @ K^T (dot4 over h) ----
        float s[4][4];
#pragma unroll
        for (int i = 0; i < 4; i++)
#pragma unroll
            for (int j = 0; j < 4; j++) s[i][j] = 0.f;

#pragma unroll
        for (int h = 0; h < HH; h += 4) {
            float4 a[4], kb[4];
#pragma unroll
            for (int i = 0; i < 4; i++)
                a[i] = *(const float4*)&Qs[(ty * 4 + i) * SQ + h];
#pragma unroll
            for (int j = 0; j < 4; j++)
                kb[j] = *(const float4*)&Ks[(tx + 16 * j) * SQ + h];
#pragma unroll
            for (int i = 0; i < 4; i++)
#pragma unroll
                for (int j = 0; j < 4; j++) {
                    s[i][j] += a[i].x * kb[j].x;
                    s[i][j] += a[i].y * kb[j].y;
                    s[i][j] += a[i].z * kb[j].z;
                    s[i][j] += a[i].w * kb[j].w;
                }
        }

        // causal mask only on the diagonal tile (k0 == q0)
        if (kt == qt) {
#pragma unroll
            for (int i = 0; i < 4; i++) {
                int r = ty * 4 + i;
#pragma unroll
                for (int j = 0; j < 4; j++)
                    if (tx + 16 * j > r) s[i][j] = -1e30f;
            }
        }

        // ---- online softmax (base-2) + write P ----
#pragma unroll
        for (int i = 0; i < 4; i++) {
            float mx = fmaxf(fmaxf(s[i][0], s[i][1]), fmaxf(s[i][2], s[i][3]));
#pragma unroll
            for (int off = 8; off >= 1; off >>= 1)
                mx = fmaxf(mx, __shfl_xor_sync(0xffffffffu, mx, off));
            float m_new = fmaxf(m_i[i], mx);
            float alpha = exp2f(m_i[i] - m_new);
            float rs = 0.f;
#pragma unroll
            for (int j = 0; j < 4; j++) {
                s[i][j] = exp2f(s[i][j] - m_new);
                rs += s[i][j];
            }
#pragma unroll
            for (int off = 8; off >= 1; off >>= 1)
                rs += __shfl_xor_sync(0xffffffffu, rs, off);
            l_i[i] = l_i[i] * alpha + rs;
            m_i[i] = m_new;
#pragma unroll
            for (int jj = 0; jj < 8; jj++) o[i][jj] *= alpha;
#pragma unroll
            for (int j = 0; j < 4; j++)
                Ps[(ty * 4 + i) * SP + tx + 16 * j] = s[i][j];
        }
        __syncthreads();

        // ---- O += P @ V ----
#pragma unroll 4
        for (int n = 0; n < BN; n++) {
            float p[4], vv[8];
#pragma unroll
            for (int i = 0; i < 4; i++) p[i] = Ps[(ty * 4 + i) * SP + n];
#pragma unroll
            for (int jj = 0; jj < 8; jj++) vv[jj] = Vs[n * SQ + tx + 16 * jj];
#pragma unroll
            for (int i = 0; i < 4; i++)
#pragma unroll
                for (int jj = 0; jj < 8; jj++) o[i][jj] += p[i] * vv[jj];
        }
        __syncthreads();   // protect K/V/P before next iteration's overwrite
    }

    // ---- epilogue: normalize and store ----
#pragma unroll
    for (int i = 0; i < 4; i++) {
        float inv = 1.f / l_i[i];
        float* op = &out[((size_t)b * TT + q0 + ty * 4 + i) * HH];
#pragma unroll
        for (int jj = 0; jj < 8; jj++)
            op[tx + 16 * jj] = o[i][jj] * inv;
    }
}

// ---------------------------------------------------------------------------
extern "C" void kernel_launch(void* const* d_in, const int* in_sizes, int n_in,
                              void* d_out, int out_size)
{
    const float* x  = (const float*)d_in[0];
    const float* Wk = (const float*)d_in[1];
    const float* Wq = (const float*)d_in[2];
    const float* Wv = (const float*)d_in[3];
    float* out = (float*)d_out;

    (void)in_sizes; (void)n_in; (void)out_size;

    // projections: q,k,v
    dim3 pgrid((BB * TT) / 64, 3);
    proj_kernel<<<pgrid, 256>>>(x, Wk, Wq, Wv);

    // attention
    const int smem_bytes = (64 * 132 * 3 + 64 * 68) * 4;   // 118784
    cudaFuncSetAttribute(attn_kernel,
                         cudaFuncAttributeMaxDynamicSharedMemorySize,
                         smem_bytes);
    attn_kernel<<<BB * NQT, 256, smem_bytes>>>(out);
}

// round 3
// speedup vs baseline: 2.0411x; 2.0359x over previous
#include <cuda_runtime.h>
#include <stdint.h>
#include <math.h>

#define BB 4
#define TT 4096
#define CC 1024
#define HH 128
#define NQT 64

// projection scratch, stored as tf32 bit patterns (q pre-scaled by H^-0.5*log2e)
__device__ uint32_t g_q[BB * TT * HH];
__device__ uint32_t g_k[BB * TT * HH];
__device__ uint32_t g_v[BB * TT * HH];

__device__ __forceinline__ uint32_t f2tf(float x) {
    uint32_t r;
    asm("cvt.rna.tf32.f32 %0, %1;" : "=r"(r) : "f"(x));
    return r;
}

__device__ __forceinline__ void mma8(float c[4],
                                     uint32_t a0, uint32_t a1, uint32_t a2, uint32_t a3,
                                     uint32_t b0, uint32_t b1)
{
    asm volatile(
        "mma.sync.aligned.m16n8k8.row.col.f32.tf32.tf32.f32 "
        "{%0,%1,%2,%3},{%4,%5,%6,%7},{%8,%9},{%0,%1,%2,%3};"
        : "+f"(c[0]), "+f"(c[1]), "+f"(c[2]), "+f"(c[3])
        : "r"(a0), "r"(a1), "r"(a2), "r"(a3), "r"(b0), "r"(b1));
}

// ---------------------------------------------------------------------------
// Projection: y = x @ W via tf32 mma. M=16384, K=1024, N=128.
// CTA 128x128, 256 threads, 8 warps in 4x2; warp tile 32x64 (2 m16 x 8 n8).
// Output written as tf32 (u32) for direct reuse as mma operands in attention.
// ---------------------------------------------------------------------------
__global__ void __launch_bounds__(256) proj_kernel(
    const float* __restrict__ x,
    const float* __restrict__ Wk,
    const float* __restrict__ Wq,
    const float* __restrict__ Wv)
{
    __shared__ uint32_t Xs[128][36];   // stride 36 -> bank = 4g+t (conflict-free)
    __shared__ uint32_t Ws[32][136];   // stride 136 -> bank = 8t+g (conflict-free)

    const int z = blockIdx.y;
    const float* W = (z == 0) ? Wq : (z == 1) ? Wk : Wv;
    uint32_t* y    = (z == 0) ? g_q : (z == 1) ? g_k : g_v;
    const float oscale = (z == 0) ? (0.08838834764831845f * 1.4426950408889634f) : 1.0f;

    const int row0 = blockIdx.x * 128;
    const int tid  = threadIdx.x;
    const int wid  = tid >> 5, lane = tid & 31;
    const int wm   = (wid >> 1) * 32, wn = (wid & 1) * 64;
    const int g    = lane >> 2, t = lane & 3;

    float acc[2][8][4];
#pragma unroll
    for (int i = 0; i < 2; i++)
#pragma unroll
        for (int j = 0; j < 8; j++)
#pragma unroll
            for (int q = 0; q < 4; q++) acc[i][j][q] = 0.f;

    for (int k0 = 0; k0 < CC; k0 += 32) {
        // X tile 128x32 (1024 float4)
#pragma unroll
        for (int u = 0; u < 4; u++) {
            int v = tid + u * 256;
            int r = v >> 3, c4 = (v & 7) << 2;
            float4 f = *(const float4*)&x[(size_t)(row0 + r) * CC + k0 + c4];
            Xs[r][c4 + 0] = f2tf(f.x); Xs[r][c4 + 1] = f2tf(f.y);
            Xs[r][c4 + 2] = f2tf(f.z); Xs[r][c4 + 3] = f2tf(f.w);
        }
        // W tile 32x128 (1024 float4)
#pragma unroll
        for (int u = 0; u < 4; u++) {
            int v = tid + u * 256;
            int r = v >> 5, c4 = (v & 31) << 2;
            float4 f = *(const float4*)&W[(size_t)(k0 + r) * HH + c4];
            Ws[r][c4 + 0] = f2tf(f.x); Ws[r][c4 + 1] = f2tf(f.y);
            Ws[r][c4 + 2] = f2tf(f.z); Ws[r][c4 + 3] = f2tf(f.w);
        }
        __syncthreads();

#pragma unroll
        for (int ks = 0; ks < 32; ks += 8) {
            uint32_t a[2][4], b[8][2];
#pragma unroll
            for (int i = 0; i < 2; i++) {
                int r = wm + i * 16;
                a[i][0] = Xs[r + g][ks + t];     a[i][1] = Xs[r + g + 8][ks + t];
                a[i][2] = Xs[r + g][ks + t + 4]; a[i][3] = Xs[r + g + 8][ks + t + 4];
            }
#pragma unroll
            for (int j = 0; j < 8; j++) {
                int c = wn + j * 8 + g;
                b[j][0] = Ws[ks + t][c];
                b[j][1] = Ws[ks + t + 4][c];
            }
#pragma unroll
            for (int i = 0; i < 2; i++)
#pragma unroll
                for (int j = 0; j < 8; j++)
                    mma8(acc[i][j], a[i][0], a[i][1], a[i][2], a[i][3], b[j][0], b[j][1]);
        }
        __syncthreads();
    }

#pragma unroll
    for (int i = 0; i < 2; i++) {
        int rlo = row0 + wm + i * 16 + g;
        int rhi = rlo + 8;
#pragma unroll
        for (int j = 0; j < 8; j++) {
            int c = wn + j * 8 + 2 * t;
            y[(size_t)rlo * HH + c]     = f2tf(acc[i][j][0] * oscale);
            y[(size_t)rlo * HH + c + 1] = f2tf(acc[i][j][1] * oscale);
            y[(size_t)rhi * HH + c]     = f2tf(acc[i][j][2] * oscale);
            y[(size_t)rhi * HH + c + 1] = f2tf(acc[i][j][3] * oscale);
        }
    }
}

// ---------------------------------------------------------------------------
// Flash attention (causal) with tf32 mma. BM=64, BN=32, 128 threads (4 warps).
// Warp w owns S/O rows [w*16, w*16+16) across the full N extent, so softmax
// row reductions stay inside one quad (2 shfls). P routed via smem (tf32).
// ---------------------------------------------------------------------------
#define SQ 132
#define SK 132
#define SV 136
#define SP 36

__global__ void __launch_bounds__(128) attn_kernel(float* __restrict__ out)
{
    extern __shared__ uint32_t smattn[];
    uint32_t* Qs = smattn;              // [64][132]
    uint32_t* Ks = Qs + 64 * SQ;        // [32][132]
    uint32_t* Vs = Ks + 32 * SK;        // [32][136]
    uint32_t* Ps = Vs + 32 * SV;        // [64][36]

    const int bid = blockIdx.x;
    const int b   = bid & 3;
    const int qt  = NQT - 1 - (bid >> 2);   // longest CTAs first
    const int q0  = qt * 64;
    const int tid = threadIdx.x;
    const int wid = tid >> 5, lane = tid & 31;
    const int g   = lane >> 2, t = lane & 3;
    const int wm  = wid * 16;

    // Q tile 64x128 (already tf32, pre-scaled)
    const uint32_t* qp = g_q + ((size_t)b * TT + q0) * HH;
#pragma unroll
    for (int u = 0; u < 16; u++) {
        int v = tid + u * 128;
        int r = v >> 5, c4 = (v & 31) << 2;
        *(uint4*)&Qs[r * SQ + c4] = *(const uint4*)&qp[(size_t)r * HH + c4];
    }

    float o[16][4];
#pragma unroll
    for (int jj = 0; jj < 16; jj++)
#pragma unroll
        for (int q = 0; q < 4; q++) o[jj][q] = 0.f;
    float m0 = -1e30f, m1 = -1e30f, l0 = 0.f, l1 = 0.f;

    __syncthreads();

    const int nkt = 2 * qt + 2;
    for (int kt = 0; kt < nkt; kt++) {
        const int k0 = kt * 32;
        const uint32_t* kp = g_k + ((size_t)b * TT + k0) * HH;
        const uint32_t* vp = g_v + ((size_t)b * TT + k0) * HH;
#pragma unroll
        for (int u = 0; u < 8; u++) {
            int v = tid + u * 128;
            int r = v >> 5, c4 = (v & 31) << 2;
            *(uint4*)&Ks[r * SK + c4] = *(const uint4*)&kp[(size_t)r * HH + c4];
            *(uint4*)&Vs[r * SV + c4] = *(const uint4*)&vp[(size_t)r * HH + c4];
        }
        __syncthreads();

        // ---- S = Q @ K^T ----
        float s[4][4];
#pragma unroll
        for (int j = 0; j < 4; j++)
#pragma unroll
            for (int q = 0; q < 4; q++) s[j][q] = 0.f;

#pragma unroll
        for (int ks = 0; ks < HH; ks += 8) {
            uint32_t a0 = Qs[(wm + g) * SQ + ks + t];
            uint32_t a1 = Qs[(wm + g + 8) * SQ + ks + t];
            uint32_t a2 = Qs[(wm + g) * SQ + ks + t + 4];
            uint32_t a3 = Qs[(wm + g + 8) * SQ + ks + t + 4];
#pragma unroll
            for (int j = 0; j < 4; j++) {
                uint32_t b0 = Ks[(j * 8 + g) * SK + ks + t];
                uint32_t b1 = Ks[(j * 8 + g) * SK + ks + t + 4];
                mma8(s[j], a0, a1, a2, a3, b0, b1);
            }
        }

        // causal mask (only near the diagonal)
        if (k0 + 31 > q0 + wm) {
            int rlo = q0 + wm + g, rhi = rlo + 8;
#pragma unroll
            for (int j = 0; j < 4; j++) {
                int c = k0 + j * 8 + 2 * t;
                if (c     > rlo) s[j][0] = -1e30f;
                if (c + 1 > rlo) s[j][1] = -1e30f;
                if (c     > rhi) s[j][2] = -1e30f;
                if (c + 1 > rhi) s[j][3] = -1e30f;
            }
        }

        // ---- online softmax (base-2 domain) ----
        float mx0 = -1e30f, mx1 = -1e30f;
#pragma unroll
        for (int j = 0; j < 4; j++) {
            mx0 = fmaxf(mx0, fmaxf(s[j][0], s[j][1]));
            mx1 = fmaxf(mx1, fmaxf(s[j][2], s[j][3]));
        }
        mx0 = fmaxf(mx0, __shfl_xor_sync(0xffffffffu, mx0, 1));
        mx0 = fmaxf(mx0, __shfl_xor_sync(0xffffffffu, mx0, 2));
        mx1 = fmaxf(mx1, __shfl_xor_sync(0xffffffffu, mx1, 1));
        mx1 = fmaxf(mx1, __shfl_xor_sync(0xffffffffu, mx1, 2));

        float mn0 = fmaxf(m0, mx0), mn1 = fmaxf(m1, mx1);
        float al0 = exp2f(m0 - mn0), al1 = exp2f(m1 - mn1);
        float rs0 = 0.f, rs1 = 0.f;
#pragma unroll
        for (int j = 0; j < 4; j++) {
            s[j][0] = exp2f(s[j][0] - mn0); s[j][1] = exp2f(s[j][1] - mn0);
            s[j][2] = exp2f(s[j][2] - mn1); s[j][3] = exp2f(s[j][3] - mn1);
            rs0 += s[j][0] + s[j][1];
            rs1 += s[j][2] + s[j][3];
        }
        rs0 += __shfl_xor_sync(0xffffffffu, rs0, 1);
        rs0 += __shfl_xor_sync(0xffffffffu, rs0, 2);
        rs1 += __shfl_xor_sync(0xffffffffu, rs1, 1);
        rs1 += __shfl_xor_sync(0xffffffffu, rs1, 2);
        l0 = l0 * al0 + rs0;  l1 = l1 * al1 + rs1;
        m0 = mn0;  m1 = mn1;

#pragma unroll
        for (int jj = 0; jj < 16; jj++) {
            o[jj][0] *= al0; o[jj][1] *= al0;
            o[jj][2] *= al1; o[jj][3] *= al1;
        }

        // P -> smem (tf32); only this warp's rows, so __syncwarp suffices
#pragma unroll
        for (int j = 0; j < 4; j++) {
            int c = j * 8 + 2 * t;
            Ps[(wm + g) * SP + c]         = f2tf(s[j][0]);
            Ps[(wm + g) * SP + c + 1]     = f2tf(s[j][1]);
            Ps[(wm + g + 8) * SP + c]     = f2tf(s[j][2]);
            Ps[(wm + g + 8) * SP + c + 1] = f2tf(s[j][3]);
        }
        __syncwarp();

        // ---- O += P @ V ----
#pragma unroll
        for (int kk = 0; kk < 32; kk += 8) {
            uint32_t a0 = Ps[(wm + g) * SP + kk + t];
            uint32_t a1 = Ps[(wm + g + 8) * SP + kk + t];
            uint32_t a2 = Ps[(wm + g) * SP + kk + t + 4];
            uint32_t a3 = Ps[(wm + g + 8) * SP + kk + t + 4];
#pragma unroll
            for (int jj = 0; jj < 16; jj++) {
                uint32_t b0 = Vs[(kk + t) * SV + jj * 8 + g];
                uint32_t b1 = Vs[(kk + t + 4) * SV + jj * 8 + g];
                mma8(o[jj], a0, a1, a2, a3, b0, b1);
            }
        }
        __syncthreads();   // protect Ks/Vs before next iteration's overwrite
    }

    // ---- epilogue ----
    float inv0 = 1.f / l0, inv1 = 1.f / l1;
    int rlo = q0 + wm + g, rhi = rlo + 8;
    float* olo = out + ((size_t)b * TT + rlo) * HH;
    float* ohi = out + ((size_t)b * TT + rhi) * HH;
#pragma unroll
    for (int jj = 0; jj < 16; jj++) {
        int c = jj * 8 + 2 * t;
        float2 v0 = make_float2(o[jj][0] * inv0, o[jj][1] * inv0);
        float2 v1 = make_float2(o[jj][2] * inv1, o[jj][3] * inv1);
        *(float2*)&olo[c] = v0;
        *(float2*)&ohi[c] = v1;
    }
}

// ---------------------------------------------------------------------------
extern "C" void kernel_launch(void* const* d_in, const int* in_sizes, int n_in,
                              void* d_out, int out_size)
{
    const float* x  = (const float*)d_in[0];
    const float* Wk = (const float*)d_in[1];
    const float* Wq = (const float*)d_in[2];
    const float* Wv = (const float*)d_in[3];
    float* out = (float*)d_out;

    (void)in_sizes; (void)n_in; (void)out_size;

    dim3 pgrid((BB * TT) / 128, 3);
    proj_kernel<<<pgrid, 256>>>(x, Wk, Wq, Wv);

    const int smem_bytes = (64 * SQ + 32 * SK + 32 * SV + 64 * SP) * 4;  // 77312
    cudaFuncSetAttribute(attn_kernel,
                         cudaFuncAttributeMaxDynamicSharedMemorySize,
                         smem_bytes);
    attn_kernel<<<BB * NQT, 128, smem_bytes>>>(out);
}

// round 4
// speedup vs baseline: 2.3566x; 1.1545x over previous
#include <cuda_runtime.h>
#include <stdint.h>
#include <math.h>

#define BB 4
#define TT 4096
#define CC 1024
#define HH 128
#define NQT 64

// projection scratch, stored as tf32 bit patterns (q pre-scaled by H^-0.5*log2e)
__device__ uint32_t g_q[BB * TT * HH];
__device__ uint32_t g_k[BB * TT * HH];
__device__ uint32_t g_v[BB * TT * HH];

__device__ __forceinline__ uint32_t f2tf(float x) {
    uint32_t r;
    asm("cvt.rna.tf32.f32 %0, %1;" : "=r"(r) : "f"(x));
    return r;
}

__device__ __forceinline__ void mma8(float c[4],
                                     uint32_t a0, uint32_t a1, uint32_t a2, uint32_t a3,
                                     uint32_t b0, uint32_t b1)
{
    asm volatile(
        "mma.sync.aligned.m16n8k8.row.col.f32.tf32.tf32.f32 "
        "{%0,%1,%2,%3},{%4,%5,%6,%7},{%8,%9},{%0,%1,%2,%3};"
        : "+f"(c[0]), "+f"(c[1]), "+f"(c[2]), "+f"(c[3])
        : "r"(a0), "r"(a1), "r"(a2), "r"(a3), "r"(b0), "r"(b1));
}

__device__ __forceinline__ void cp16(uint32_t dst, const void* src) {
    asm volatile("cp.async.cg.shared.global [%0], [%1], 16;"
                 :: "r"(dst), "l"(src));
}

// ---------------------------------------------------------------------------
// Projection: y = x @ W via tf32 mma. M=16384, K=1024, N=128. (unchanged R2)
// ---------------------------------------------------------------------------
__global__ void __launch_bounds__(256) proj_kernel(
    const float* __restrict__ x,
    const float* __restrict__ Wk,
    const float* __restrict__ Wq,
    const float* __restrict__ Wv)
{
    __shared__ uint32_t Xs[128][36];
    __shared__ uint32_t Ws[32][136];

    const int z = blockIdx.y;
    const float* W = (z == 0) ? Wq : (z == 1) ? Wk : Wv;
    uint32_t* y    = (z == 0) ? g_q : (z == 1) ? g_k : g_v;
    const float oscale = (z == 0) ? (0.08838834764831845f * 1.4426950408889634f) : 1.0f;

    const int row0 = blockIdx.x * 128;
    const int tid  = threadIdx.x;
    const int wid  = tid >> 5, lane = tid & 31;
    const int wm   = (wid >> 1) * 32, wn = (wid & 1) * 64;
    const int g    = lane >> 2, t = lane & 3;

    float acc[2][8][4];
#pragma unroll
    for (int i = 0; i < 2; i++)
#pragma unroll
        for (int j = 0; j < 8; j++)
#pragma unroll
            for (int q = 0; q < 4; q++) acc[i][j][q] = 0.f;

    for (int k0 = 0; k0 < CC; k0 += 32) {
#pragma unroll
        for (int u = 0; u < 4; u++) {
            int v = tid + u * 256;
            int r = v >> 3, c4 = (v & 7) << 2;
            float4 f = *(const float4*)&x[(size_t)(row0 + r) * CC + k0 + c4];
            Xs[r][c4 + 0] = f2tf(f.x); Xs[r][c4 + 1] = f2tf(f.y);
            Xs[r][c4 + 2] = f2tf(f.z); Xs[r][c4 + 3] = f2tf(f.w);
        }
#pragma unroll
        for (int u = 0; u < 4; u++) {
            int v = tid + u * 256;
            int r = v >> 5, c4 = (v & 31) << 2;
            float4 f = *(const float4*)&W[(size_t)(k0 + r) * HH + c4];
            Ws[r][c4 + 0] = f2tf(f.x); Ws[r][c4 + 1] = f2tf(f.y);
            Ws[r][c4 + 2] = f2tf(f.z); Ws[r][c4 + 3] = f2tf(f.w);
        }
        __syncthreads();

#pragma unroll
        for (int ks = 0; ks < 32; ks += 8) {
            uint32_t a[2][4], bfr[8][2];
#pragma unroll
            for (int i = 0; i < 2; i++) {
                int r = wm + i * 16;
                a[i][0] = Xs[r + g][ks + t];     a[i][1] = Xs[r + g + 8][ks + t];
                a[i][2] = Xs[r + g][ks + t + 4]; a[i][3] = Xs[r + g + 8][ks + t + 4];
            }
#pragma unroll
            for (int j = 0; j < 8; j++) {
                int c = wn + j * 8 + g;
                bfr[j][0] = Ws[ks + t][c];
                bfr[j][1] = Ws[ks + t + 4][c];
            }
#pragma unroll
            for (int i = 0; i < 2; i++)
#pragma unroll
                for (int j = 0; j < 8; j++)
                    mma8(acc[i][j], a[i][0], a[i][1], a[i][2], a[i][3],
                         bfr[j][0], bfr[j][1]);
        }
        __syncthreads();
    }

#pragma unroll
    for (int i = 0; i < 2; i++) {
        int rlo = row0 + wm + i * 16 + g;
        int rhi = rlo + 8;
#pragma unroll
        for (int j = 0; j < 8; j++) {
            int c = wn + j * 8 + 2 * t;
            y[(size_t)rlo * HH + c]     = f2tf(acc[i][j][0] * oscale);
            y[(size_t)rlo * HH + c + 1] = f2tf(acc[i][j][1] * oscale);
            y[(size_t)rhi * HH + c]     = f2tf(acc[i][j][2] * oscale);
            y[(size_t)rhi * HH + c + 1] = f2tf(acc[i][j][3] * oscale);
        }
    }
}

// ---------------------------------------------------------------------------
// Flash attention (causal), tf32 mma, BM=64, BN=32, 128 threads (4 warps).
// cp.async double-buffered K/V; balanced long+short CTA pairing that exploits
// smid = LUT[bid % 148] co-placement of bid s and s+148.
// ---------------------------------------------------------------------------
#define SQ 132
#define SK 132
#define SV 136
#define SP 36
#define KBUF (32 * SK)
#define VBUF (32 * SV)

__global__ void __launch_bounds__(128) attn_kernel(float* __restrict__ out)
{
    extern __shared__ uint32_t smattn[];
    uint32_t* Qs = smattn;              // [64][132]
    uint32_t* Ks = Qs + 64 * SQ;        // 2 x [32][132]
    uint32_t* Vs = Ks + 2 * KBUF;       // 2 x [32][136]
    uint32_t* Ps = Vs + 2 * VBUF;       // [64][36]

    // ---- balanced schedule: pair bid s with s+148 (same SM via LUT[bid%148])
    const int bid = blockIdx.x;
    const int r   = (bid < 148) ? bid : 403 - bid;   // rank 0..255, desc work
    const int qt  = 63 - (r >> 2);
    const int b   = r & 3;
    const int q0  = qt * 64;

    const int tid = threadIdx.x;
    const int wid = tid >> 5, lane = tid & 31;
    const int g   = lane >> 2, t = lane & 3;
    const int wm  = wid * 16;

    uint32_t smb;
    {
        void* p = (void*)smattn;
        smb = (uint32_t)__cvta_generic_to_shared(p);
    }
    const uint32_t smKs = smb + 64 * SQ * 4;
    const uint32_t smVs = smKs + 2 * KBUF * 4;

    const int nkt = 2 * qt + 2;

    // prologue: prefetch K/V tile kt=0 into buffer 0
    {
        const uint32_t* kp = g_k + ((size_t)b * TT) * HH;
        const uint32_t* vp = g_v + ((size_t)b * TT) * HH;
#pragma unroll
        for (int u = 0; u < 8; u++) {
            int v = tid + u * 128;
            int rr = v >> 5, c4 = (v & 31) << 2;
            cp16(smKs + (uint32_t)(rr * SK + c4) * 4, kp + (size_t)rr * HH + c4);
            cp16(smVs + (uint32_t)(rr * SV + c4) * 4, vp + (size_t)rr * HH + c4);
        }
        asm volatile("cp.async.commit_group;");
    }

    // Q tile 64x128 (already tf32, pre-scaled)
    const uint32_t* qp = g_q + ((size_t)b * TT + q0) * HH;
#pragma unroll
    for (int u = 0; u < 16; u++) {
        int v = tid + u * 128;
        int rr = v >> 5, c4 = (v & 31) << 2;
        *(uint4*)&Qs[rr * SQ + c4] = *(const uint4*)&qp[(size_t)rr * HH + c4];
    }

    float o[16][4];
#pragma unroll
    for (int jj = 0; jj < 16; jj++)
#pragma unroll
        for (int q = 0; q < 4; q++) o[jj][q] = 0.f;
    float m0 = -1e30f, m1 = -1e30f, l0 = 0.f, l1 = 0.f;

    for (int kt = 0; kt < nkt; kt++) {
        __syncthreads();   // all warps done with previous compute (buffers free)

        if (kt + 1 < nkt) {
            const int k0n = (kt + 1) * 32;
            const uint32_t* kp = g_k + ((size_t)b * TT + k0n) * HH;
            const uint32_t* vp = g_v + ((size_t)b * TT + k0n) * HH;
            const uint32_t kd = smKs + (uint32_t)(((kt + 1) & 1) * KBUF) * 4;
            const uint32_t vd = smVs + (uint32_t)(((kt + 1) & 1) * VBUF) * 4;
#pragma unroll
            for (int u = 0; u < 8; u++) {
                int v = tid + u * 128;
                int rr = v >> 5, c4 = (v & 31) << 2;
                cp16(kd + (uint32_t)(rr * SK + c4) * 4, kp + (size_t)rr * HH + c4);
                cp16(vd + (uint32_t)(rr * SV + c4) * 4, vp + (size_t)rr * HH + c4);
            }
            asm volatile("cp.async.commit_group;");
            asm volatile("cp.async.wait_group 1;");   // tile kt landed
        } else {
            asm volatile("cp.async.wait_group 0;");
        }
        __syncthreads();   // tile kt visible to all warps

        const uint32_t* Kc = Ks + (kt & 1) * KBUF;
        const uint32_t* Vc = Vs + (kt & 1) * VBUF;
        const int k0 = kt * 32;

        // ---- S = Q @ K^T ----
        float s[4][4];
#pragma unroll
        for (int j = 0; j < 4; j++)
#pragma unroll
            for (int q = 0; q < 4; q++) s[j][q] = 0.f;

#pragma unroll
        for (int ks = 0; ks < HH; ks += 8) {
            uint32_t a0 = Qs[(wm + g) * SQ + ks + t];
            uint32_t a1 = Qs[(wm + g + 8) * SQ + ks + t];
            uint32_t a2 = Qs[(wm + g) * SQ + ks + t + 4];
            uint32_t a3 = Qs[(wm + g + 8) * SQ + ks + t + 4];
#pragma unroll
            for (int j = 0; j < 4; j++) {
                uint32_t b0 = Kc[(j * 8 + g) * SK + ks + t];
                uint32_t b1 = Kc[(j * 8 + g) * SK + ks + t + 4];
                mma8(s[j], a0, a1, a2, a3, b0, b1);
            }
        }

        // causal mask (only near the diagonal)
        if (k0 + 31 > q0 + wm) {
            int rlo = q0 + wm + g, rhi = rlo + 8;
#pragma unroll
            for (int j = 0; j < 4; j++) {
                int c = k0 + j * 8 + 2 * t;
                if (c     > rlo) s[j][0] = -1e30f;
                if (c + 1 > rlo) s[j][1] = -1e30f;
                if (c     > rhi) s[j][2] = -1e30f;
                if (c + 1 > rhi) s[j][3] = -1e30f;
            }
        }

        // ---- online softmax (base-2 domain) ----
        float mx0 = -1e30f, mx1 = -1e30f;
#pragma unroll
        for (int j = 0; j < 4; j++) {
            mx0 = fmaxf(mx0, fmaxf(s[j][0], s[j][1]));
            mx1 = fmaxf(mx1, fmaxf(s[j][2], s[j][3]));
        }
        mx0 = fmaxf(mx0, __shfl_xor_sync(0xffffffffu, mx0, 1));
        mx0 = fmaxf(mx0, __shfl_xor_sync(0xffffffffu, mx0, 2));
        mx1 = fmaxf(mx1, __shfl_xor_sync(0xffffffffu, mx1, 1));
        mx1 = fmaxf(mx1, __shfl_xor_sync(0xffffffffu, mx1, 2));

        float mn0 = fmaxf(m0, mx0), mn1 = fmaxf(m1, mx1);
        float al0 = exp2f(m0 - mn0), al1 = exp2f(m1 - mn1);
        float rs0 = 0.f, rs1 = 0.f;
#pragma unroll
        for (int j = 0; j < 4; j++) {
            s[j][0] = exp2f(s[j][0] - mn0); s[j][1] = exp2f(s[j][1] - mn0);
            s[j][2] = exp2f(s[j][2] - mn1); s[j][3] = exp2f(s[j][3] - mn1);
            rs0 += s[j][0] + s[j][1];
            rs1 += s[j][2] + s[j][3];
        }
        rs0 += __shfl_xor_sync(0xffffffffu, rs0, 1);
        rs0 += __shfl_xor_sync(0xffffffffu, rs0, 2);
        rs1 += __shfl_xor_sync(0xffffffffu, rs1, 1);
        rs1 += __shfl_xor_sync(0xffffffffu, rs1, 2);
        l0 = l0 * al0 + rs0;  l1 = l1 * al1 + rs1;
        m0 = mn0;  m1 = mn1;

#pragma unroll
        for (int jj = 0; jj < 16; jj++) {
            o[jj][0] *= al0; o[jj][1] *= al0;
            o[jj][2] *= al1; o[jj][3] *= al1;
        }

        // P -> smem (tf32); only this warp's rows, so syncwarp suffices
#pragma unroll
        for (int j = 0; j < 4; j++) {
            int c = j * 8 + 2 * t;
            Ps[(wm + g) * SP + c]         = f2tf(s[j][0]);
            Ps[(wm + g) * SP + c + 1]     = f2tf(s[j][1]);
            Ps[(wm + g + 8) * SP + c]     = f2tf(s[j][2]);
            Ps[(wm + g + 8) * SP + c + 1] = f2tf(s[j][3]);
        }
        __syncwarp();

        // ---- O += P @ V ----
#pragma unroll
        for (int kk = 0; kk < 32; kk += 8) {
            uint32_t a0 = Ps[(wm + g) * SP + kk + t];
            uint32_t a1 = Ps[(wm + g + 8) * SP + kk + t];
            uint32_t a2 = Ps[(wm + g) * SP + kk + t + 4];
            uint32_t a3 = Ps[(wm + g + 8) * SP + kk + t + 4];
#pragma unroll
            for (int jj = 0; jj < 16; jj++) {
                uint32_t b0 = Vc[(kk + t) * SV + jj * 8 + g];
                uint32_t b1 = Vc[(kk + t + 4) * SV + jj * 8 + g];
                mma8(o[jj], a0, a1, a2, a3, b0, b1);
            }
        }
    }

    // ---- epilogue ----
    float inv0 = 1.f / l0, inv1 = 1.f / l1;
    int rlo = q0 + wm + g, rhi = rlo + 8;
    float* olo = out + ((size_t)b * TT + rlo) * HH;
    float* ohi = out + ((size_t)b * TT + rhi) * HH;
#pragma unroll
    for (int jj = 0; jj < 16; jj++) {
        int c = jj * 8 + 2 * t;
        float2 v0 = make_float2(o[jj][0] * inv0, o[jj][1] * inv0);
        float2 v1 = make_float2(o[jj][2] * inv1, o[jj][3] * inv1);
        *(float2*)&olo[c] = v0;
        *(float2*)&ohi[c] = v1;
    }
}

// ---------------------------------------------------------------------------
extern "C" void kernel_launch(void* const* d_in, const int* in_sizes, int n_in,
                              void* d_out, int out_size)
{
    const float* x  = (const float*)d_in[0];
    const float* Wk = (const float*)d_in[1];
    const float* Wq = (const float*)d_in[2];
    const float* Wv = (const float*)d_in[3];
    float* out = (float*)d_out;

    (void)in_sizes; (void)n_in; (void)out_size;

    dim3 pgrid((BB * TT) / 128, 3);
    proj_kernel<<<pgrid, 256>>>(x, Wk, Wq, Wv);

    const int smem_bytes = (64 * SQ + 2 * KBUF + 2 * VBUF + 64 * SP) * 4; // 111616
    cudaFuncSetAttribute(attn_kernel,
                         cudaFuncAttributeMaxDynamicSharedMemorySize,
                         smem_bytes);
    attn_kernel<<<BB * NQT, 128, smem_bytes>>>(out);
}

// round 5
// speedup vs baseline: 3.6552x; 1.5510x over previous
#include <cuda_runtime.h>
#include <stdint.h>
#include <math.h>

#define BB 4
#define TT 4096
#define CC 1024
#define HH 128
#define NQT 64

// projection scratch, stored as tf32 bit patterns (q pre-scaled by H^-0.5*log2e)
__device__ uint32_t g_q[BB * TT * HH];
__device__ uint32_t g_k[BB * TT * HH];
__device__ uint32_t g_v[BB * TT * HH];

__device__ __forceinline__ uint32_t f2tf(float x) {
    uint32_t r;
    asm("cvt.rna.tf32.f32 %0, %1;" : "=r"(r) : "f"(x));
    return r;
}

__device__ __forceinline__ void mma8(float c[4],
                                     uint32_t a0, uint32_t a1, uint32_t a2, uint32_t a3,
                                     uint32_t b0, uint32_t b1)
{
    asm volatile(
        "mma.sync.aligned.m16n8k8.row.col.f32.tf32.tf32.f32 "
        "{%0,%1,%2,%3},{%4,%5,%6,%7},{%8,%9},{%0,%1,%2,%3};"
        : "+f"(c[0]), "+f"(c[1]), "+f"(c[2]), "+f"(c[3])
        : "r"(a0), "r"(a1), "r"(a2), "r"(a3), "r"(b0), "r"(b1));
}

__device__ __forceinline__ void cp16(uint32_t dst, const void* src) {
    asm volatile("cp.async.cg.shared.global [%0], [%1], 16;"
                 :: "r"(dst), "l"(src));
}

// ---------------------------------------------------------------------------
// Projection: y = x @ W via tf32 mma. M=16384, K=1024, N=128.
// cp.async double-buffered stages (raw fp32), cvt at fragment load
// (numerically identical: same rna cvt on same values). One barrier/iter.
// ---------------------------------------------------------------------------
#define PXS 4608   // 128*36 floats per X stage
#define PWS 4352   // 32*136 floats per W stage

__global__ void __launch_bounds__(256, 2) proj_kernel(
    const float* __restrict__ x,
    const float* __restrict__ Wk,
    const float* __restrict__ Wq,
    const float* __restrict__ Wv)
{
    extern __shared__ float psm[];
    // layout: X stages [0, PXS), [PXS, 2*PXS); W stages at 2*PXS + st*PWS

    const int z = blockIdx.y;
    const float* W = (z == 0) ? Wq : (z == 1) ? Wk : Wv;
    uint32_t* y    = (z == 0) ? g_q : (z == 1) ? g_k : g_v;
    const float oscale = (z == 0) ? (0.08838834764831845f * 1.4426950408889634f) : 1.0f;

    const int row0 = blockIdx.x * 128;
    const int tid  = threadIdx.x;
    const int wid  = tid >> 5, lane = tid & 31;
    const int wm   = (wid >> 1) * 32, wn = (wid & 1) * 64;
    const int g    = lane >> 2, t = lane & 3;

    uint32_t smb = (uint32_t)__cvta_generic_to_shared((void*)psm);

    float acc[2][8][4];
#pragma unroll
    for (int i = 0; i < 2; i++)
#pragma unroll
        for (int j = 0; j < 8; j++)
#pragma unroll
            for (int q = 0; q < 4; q++) acc[i][j][q] = 0.f;

    // prologue: stage 0 <- k0 = 0
    {
        const uint32_t xd = smb;
        const uint32_t wd = smb + 2 * PXS * 4;
#pragma unroll
        for (int u = 0; u < 4; u++) {
            int v = tid + u * 256;
            int rx = v >> 3, cx = (v & 7) << 2;
            cp16(xd + (uint32_t)(rx * 36 + cx) * 4,
                 &x[(size_t)(row0 + rx) * CC + cx]);
            int rw = v >> 5, cw = (v & 31) << 2;
            cp16(wd + (uint32_t)(rw * 136 + cw) * 4,
                 &W[(size_t)rw * HH + cw]);
        }
        asm volatile("cp.async.commit_group;");
    }

    for (int k0 = 0; k0 < CC; k0 += 32) {
        asm volatile("cp.async.wait_group 0;");
        __syncthreads();

        const int st = (k0 >> 5) & 1;
        if (k0 + 32 < CC) {
            const int sn = st ^ 1;
            const uint32_t xd = smb + (uint32_t)(sn * PXS) * 4;
            const uint32_t wd = smb + (uint32_t)(2 * PXS + sn * PWS) * 4;
#pragma unroll
            for (int u = 0; u < 4; u++) {
                int v = tid + u * 256;
                int rx = v >> 3, cx = (v & 7) << 2;
                cp16(xd + (uint32_t)(rx * 36 + cx) * 4,
                     &x[(size_t)(row0 + rx) * CC + k0 + 32 + cx]);
                int rw = v >> 5, cw = (v & 31) << 2;
                cp16(wd + (uint32_t)(rw * 136 + cw) * 4,
                     &W[(size_t)(k0 + 32 + rw) * HH + cw]);
            }
            asm volatile("cp.async.commit_group;");
        }

        const float* Xs = psm + st * PXS;
        const float* Ws = psm + 2 * PXS + st * PWS;

#pragma unroll
        for (int ks = 0; ks < 32; ks += 8) {
            uint32_t a[2][4], bfr[8][2];
#pragma unroll
            for (int i = 0; i < 2; i++) {
                int r = wm + i * 16;
                a[i][0] = f2tf(Xs[(r + g) * 36 + ks + t]);
                a[i][1] = f2tf(Xs[(r + g + 8) * 36 + ks + t]);
                a[i][2] = f2tf(Xs[(r + g) * 36 + ks + t + 4]);
                a[i][3] = f2tf(Xs[(r + g + 8) * 36 + ks + t + 4]);
            }
#pragma unroll
            for (int j = 0; j < 8; j++) {
                int c = wn + j * 8 + g;
                bfr[j][0] = f2tf(Ws[(ks + t) * 136 + c]);
                bfr[j][1] = f2tf(Ws[(ks + t + 4) * 136 + c]);
            }
#pragma unroll
            for (int i = 0; i < 2; i++)
#pragma unroll
                for (int j = 0; j < 8; j++)
                    mma8(acc[i][j], a[i][0], a[i][1], a[i][2], a[i][3],
                         bfr[j][0], bfr[j][1]);
        }
    }

#pragma unroll
    for (int i = 0; i < 2; i++) {
        int rlo = row0 + wm + i * 16 + g;
        int rhi = rlo + 8;
#pragma unroll
        for (int j = 0; j < 8; j++) {
            int c = wn + j * 8 + 2 * t;
            y[(size_t)rlo * HH + c]     = f2tf(acc[i][j][0] * oscale);
            y[(size_t)rlo * HH + c + 1] = f2tf(acc[i][j][1] * oscale);
            y[(size_t)rhi * HH + c]     = f2tf(acc[i][j][2] * oscale);
            y[(size_t)rhi * HH + c + 1] = f2tf(acc[i][j][3] * oscale);
        }
    }
}

// ---------------------------------------------------------------------------
// Flash attention (causal), tf32 mma, BM=64, BN=32, 128 threads (4 warps).
// Q fragments live in registers (no Qs smem, no per-iter Q LDS).
// Single barrier per iteration: wait -> sync -> prefetch kt+1 -> compute kt.
// Balanced long+short CTA pairing via smid = LUT[bid % 148].
// ---------------------------------------------------------------------------
#define SK 132
#define SV 136
#define SP 36
#define KBUF (32 * SK)
#define VBUF (32 * SV)

__global__ void __launch_bounds__(128, 2) attn_kernel(float* __restrict__ out)
{
    extern __shared__ uint32_t smattn[];
    uint32_t* Ks = smattn;              // 2 x [32][132]
    uint32_t* Vs = Ks + 2 * KBUF;       // 2 x [32][136]
    uint32_t* Ps = Vs + 2 * VBUF;       // [64][36]

    // ---- balanced schedule: pair bid s with s+148 (same SM via LUT[bid%148])
    const int bid = blockIdx.x;
    const int r   = (bid < 148) ? bid : 403 - bid;   // rank 0..255, desc work
    const int qt  = 63 - (r >> 2);
    const int b   = r & 3;
    const int q0  = qt * 64;

    const int tid = threadIdx.x;
    const int wid = tid >> 5, lane = tid & 31;
    const int g   = lane >> 2, t = lane & 3;
    const int wm  = wid * 16;

    const uint32_t smb  = (uint32_t)__cvta_generic_to_shared((void*)smattn);
    const uint32_t smKs = smb;
    const uint32_t smVs = smb + 2 * KBUF * 4;

    const int nkt = 2 * qt + 2;

    // prologue: prefetch K/V tile 0 into buffer 0
    {
        const uint32_t* kp = g_k + ((size_t)b * TT) * HH;
        const uint32_t* vp = g_v + ((size_t)b * TT) * HH;
#pragma unroll
        for (int u = 0; u < 8; u++) {
            int v = tid + u * 128;
            int rr = v >> 5, c4 = (v & 31) << 2;
            cp16(smKs + (uint32_t)(rr * SK + c4) * 4, kp + (size_t)rr * HH + c4);
            cp16(smVs + (uint32_t)(rr * SV + c4) * 4, vp + (size_t)rr * HH + c4);
        }
        asm volatile("cp.async.commit_group;");
    }

    // Q fragments -> registers (one-time; g_q already tf32 & pre-scaled)
    uint4 aq[16];
    {
        const uint32_t* qrow = g_q + ((size_t)b * TT + q0 + wm) * HH;
#pragma unroll
        for (int ks = 0; ks < 16; ks++) {
            aq[ks].x = qrow[(size_t)g * HH + ks * 8 + t];
            aq[ks].y = qrow[(size_t)(g + 8) * HH + ks * 8 + t];
            aq[ks].z = qrow[(size_t)g * HH + ks * 8 + t + 4];
            aq[ks].w = qrow[(size_t)(g + 8) * HH + ks * 8 + t + 4];
        }
    }

    float o[16][4];
#pragma unroll
    for (int jj = 0; jj < 16; jj++)
#pragma unroll
        for (int q = 0; q < 4; q++) o[jj][q] = 0.f;
    float m0 = -1e30f, m1 = -1e30f, l0 = 0.f, l1 = 0.f;

    for (int kt = 0; kt < nkt; kt++) {
        asm volatile("cp.async.wait_group 0;");
        __syncthreads();   // tile kt visible everywhere; buffer kt-1 free

        if (kt + 1 < nkt) {
            const int k0n = (kt + 1) * 32;
            const uint32_t* kp = g_k + ((size_t)b * TT + k0n) * HH;
            const uint32_t* vp = g_v + ((size_t)b * TT + k0n) * HH;
            const uint32_t kd = smKs + (uint32_t)(((kt + 1) & 1) * KBUF) * 4;
            const uint32_t vd = smVs + (uint32_t)(((kt + 1) & 1) * VBUF) * 4;
#pragma unroll
            for (int u = 0; u < 8; u++) {
                int v = tid + u * 128;
                int rr = v >> 5, c4 = (v & 31) << 2;
                cp16(kd + (uint32_t)(rr * SK + c4) * 4, kp + (size_t)rr * HH + c4);
                cp16(vd + (uint32_t)(rr * SV + c4) * 4, vp + (size_t)rr * HH + c4);
            }
            asm volatile("cp.async.commit_group;");
        }

        const uint32_t* Kc = Ks + (kt & 1) * KBUF;
        const uint32_t* Vc = Vs + (kt & 1) * VBUF;
        const int k0 = kt * 32;

        // ---- S = Q @ K^T (Q fragments from registers) ----
        float s[4][4];
#pragma unroll
        for (int j = 0; j < 4; j++)
#pragma unroll
            for (int q = 0; q < 4; q++) s[j][q] = 0.f;

#pragma unroll
        for (int ks = 0; ks < 16; ks++) {
            const uint4 a = aq[ks];
#pragma unroll
            for (int j = 0; j < 4; j++) {
                uint32_t b0 = Kc[(j * 8 + g) * SK + ks * 8 + t];
                uint32_t b1 = Kc[(j * 8 + g) * SK + ks * 8 + t + 4];
                mma8(s[j], a.x, a.y, a.z, a.w, b0, b1);
            }
        }

        // causal mask (only near the diagonal)
        if (k0 + 31 > q0 + wm) {
            int rlo = q0 + wm + g, rhi = rlo + 8;
#pragma unroll
            for (int j = 0; j < 4; j++) {
                int c = k0 + j * 8 + 2 * t;
                if (c     > rlo) s[j][0] = -1e30f;
                if (c + 1 > rlo) s[j][1] = -1e30f;
                if (c     > rhi) s[j][2] = -1e30f;
                if (c + 1 > rhi) s[j][3] = -1e30f;
            }
        }

        // ---- online softmax (base-2 domain) ----
        float mx0 = -1e30f, mx1 = -1e30f;
#pragma unroll
        for (int j = 0; j < 4; j++) {
            mx0 = fmaxf(mx0, fmaxf(s[j][0], s[j][1]));
            mx1 = fmaxf(mx1, fmaxf(s[j][2], s[j][3]));
        }
        mx0 = fmaxf(mx0, __shfl_xor_sync(0xffffffffu, mx0, 1));
        mx0 = fmaxf(mx0, __shfl_xor_sync(0xffffffffu, mx0, 2));
        mx1 = fmaxf(mx1, __shfl_xor_sync(0xffffffffu, mx1, 1));
        mx1 = fmaxf(mx1, __shfl_xor_sync(0xffffffffu, mx1, 2));

        float mn0 = fmaxf(m0, mx0), mn1 = fmaxf(m1, mx1);
        float al0 = exp2f(m0 - mn0), al1 = exp2f(m1 - mn1);
        float rs0 = 0.f, rs1 = 0.f;
#pragma unroll
        for (int j = 0; j < 4; j++) {
            s[j][0] = exp2f(s[j][0] - mn0); s[j][1] = exp2f(s[j][1] - mn0);
            s[j][2] = exp2f(s[j][2] - mn1); s[j][3] = exp2f(s[j][3] - mn1);
            rs0 += s[j][0] + s[j][1];
            rs1 += s[j][2] + s[j][3];
        }
        rs0 += __shfl_xor_sync(0xffffffffu, rs0, 1);
        rs0 += __shfl_xor_sync(0xffffffffu, rs0, 2);
        rs1 += __shfl_xor_sync(0xffffffffu, rs1, 1);
        rs1 += __shfl_xor_sync(0xffffffffu, rs1, 2);
        l0 = l0 * al0 + rs0;  l1 = l1 * al1 + rs1;
        m0 = mn0;  m1 = mn1;

#pragma unroll
        for (int jj = 0; jj < 16; jj++) {
            o[jj][0] *= al0; o[jj][1] *= al0;
            o[jj][2] *= al1; o[jj][3] *= al1;
        }

        // P -> smem (tf32); only this warp's rows, so syncwarp suffices
#pragma unroll
        for (int j = 0; j < 4; j++) {
            int c = j * 8 + 2 * t;
            Ps[(wm + g) * SP + c]         = f2tf(s[j][0]);
            Ps[(wm + g) * SP + c + 1]     = f2tf(s[j][1]);
            Ps[(wm + g + 8) * SP + c]     = f2tf(s[j][2]);
            Ps[(wm + g + 8) * SP + c + 1] = f2tf(s[j][3]);
        }
        __syncwarp();

        // ---- O += P @ V ----
#pragma unroll
        for (int kk = 0; kk < 32; kk += 8) {
            uint32_t a0 = Ps[(wm + g) * SP + kk + t];
            uint32_t a1 = Ps[(wm + g + 8) * SP + kk + t];
            uint32_t a2 = Ps[(wm + g) * SP + kk + t + 4];
            uint32_t a3 = Ps[(wm + g + 8) * SP + kk + t + 4];
#pragma unroll
            for (int jj = 0; jj < 16; jj++) {
                uint32_t b0 = Vc[(kk + t) * SV + jj * 8 + g];
                uint32_t b1 = Vc[(kk + t + 4) * SV + jj * 8 + g];
                mma8(o[jj], a0, a1, a2, a3, b0, b1);
            }
        }
    }

    // ---- epilogue ----
    float inv0 = 1.f / l0, inv1 = 1.f / l1;
    int rlo = q0 + wm + g, rhi = rlo + 8;
    float* olo = out + ((size_t)b * TT + rlo) * HH;
    float* ohi = out + ((size_t)b * TT + rhi) * HH;
#pragma unroll
    for (int jj = 0; jj < 16; jj++) {
        int c = jj * 8 + 2 * t;
        float2 v0 = make_float2(o[jj][0] * inv0, o[jj][1] * inv0);
        float2 v1 = make_float2(o[jj][2] * inv1, o[jj][3] * inv1);
        *(float2*)&olo[c] = v0;
        *(float2*)&ohi[c] = v1;
    }
}

// ---------------------------------------------------------------------------
extern "C" void kernel_launch(void* const* d_in, const int* in_sizes, int n_in,
                              void* d_out, int out_size)
{
    const float* x  = (const float*)d_in[0];
    const float* Wk = (const float*)d_in[1];
    const float* Wq = (const float*)d_in[2];
    const float* Wv = (const float*)d_in[3];
    float* out = (float*)d_out;

    (void)in_sizes; (void)n_in; (void)out_size;

    const int proj_smem = (2 * PXS + 2 * PWS) * 4;   // 71680
    cudaFuncSetAttribute(proj_kernel,
                         cudaFuncAttributeMaxDynamicSharedMemorySize,
                         proj_smem);
    dim3 pgrid((BB * TT) / 128, 3);
    proj_kernel<<<pgrid, 256, proj_smem>>>(x, Wk, Wq, Wv);

    const int attn_smem = (2 * KBUF + 2 * VBUF + 64 * SP) * 4;  // 77824
    cudaFuncSetAttribute(attn_kernel,
                         cudaFuncAttributeMaxDynamicSharedMemorySize,
                         attn_smem);
    attn_kernel<<<BB * NQT, 128, attn_smem>>>(out);
}